// round 1
// baseline (speedup 1.0000x reference)
#include <cuda_runtime.h>
#include <math.h>

#define NN   8192     // nodes
#define FIN  64       // input features
#define HH   128      // hidden
#define AA   8192     // action size
#define CAP  128      // max unique out-degree bucket capacity

// ---------------- device scratch (static, no allocations) ----------------
static __device__ unsigned g_bitmap[NN * (NN / 32)];   // 8 MB dedup bitmap
static __device__ int      g_cnt[NN];                  // unique out-degree
static __device__ int      g_cols[NN * CAP];           // bucketed CSR cols (4 MB)
static __device__ float    g_dinv[NN];
static __device__ float    g_ax [NN * FIN];            // A_n @ x
static __device__ float    g_h1 [NN * HH];             // layer-1 output
static __device__ float    g_ah1[NN * HH];             // A_n @ h1
static __device__ float    g_h2 [NN * HH];             // layer-2 output
static __device__ float    g_rowsum[NN];
static __device__ float    g_graph[HH];
static __device__ float    g_af[64];                   // actor hidden
static __device__ float    g_logits[AA];
static __device__ float    g_red[4];                   // pool max, pool sum, logit max, logit 1/sum
static __device__ int      g_is64;

// ---------------- kernels ----------------

// Detect whether edge_index arrived as int64 (odd int32 words are all high-words == 0)
__global__ void k_detect(const int* __restrict__ e) {
    if (threadIdx.x == 0) {
        int all0 = 1;
        #pragma unroll
        for (int k = 0; k < 32; k++)
            if (e[2 * k + 1] != 0) all0 = 0;
        g_is64 = all0;
    }
}

__global__ void k_clear() {
    const int total4 = (NN * (NN / 32)) / 4;   // uint4 count
    uint4* bm = reinterpret_cast<uint4*>(g_bitmap);
    int i = blockIdx.x * blockDim.x + threadIdx.x;
    int stride = gridDim.x * blockDim.x;
    uint4 z = make_uint4(0u, 0u, 0u, 0u);
    for (int w = i; w < total4; w += stride) bm[w] = z;
    if (i < NN) g_cnt[i] = 0;
}

__global__ void k_dedup(const int* __restrict__ e, int E) {
    int idx = blockIdx.x * blockDim.x + threadIdx.x;
    if (idx >= E) return;
    int r, c;
    if (g_is64) { r = e[2 * idx]; c = e[2 * (E + idx)]; }
    else        { r = e[idx];     c = e[E + idx]; }
    unsigned lin = (unsigned)r * NN + (unsigned)c;   // < 2^26
    unsigned w = lin >> 5, b = lin & 31u;
    unsigned old = atomicOr(&g_bitmap[w], 1u << b);
    if (!((old >> b) & 1u)) {
        int pos = atomicAdd(&g_cnt[r], 1);
        if (pos < CAP) g_cols[r * CAP + pos] = c;
    }
}

__global__ void k_dinv() {
    int i = blockIdx.x * blockDim.x + threadIdx.x;
    if (i < NN) {
        int d = min(g_cnt[i], CAP) + 1;   // +1 self loop column of eye
        g_dinv[i] = 1.0f / sqrtf((float)d);
    }
}

// SpMM layer 1: g_ax = A_n @ x   (F = 64, warp per row, 2 feats/lane)
__global__ void k_spmm1(const float* __restrict__ x) {
    int warp = (blockIdx.x * blockDim.x + threadIdx.x) >> 5;
    int lane = threadIdx.x & 31;
    if (warp >= NN) return;
    int r = warp;
    int cnt = min(g_cnt[r], CAP);
    float dr = g_dinv[r];
    float a0 = dr * x[r * FIN + lane];
    float a1 = dr * x[r * FIN + 32 + lane];
    for (int k = 0; k < cnt; k++) {
        int c = g_cols[r * CAP + k];
        float dc = g_dinv[c];
        a0 += dc * x[c * FIN + lane];
        a1 += dc * x[c * FIN + 32 + lane];
    }
    g_ax[r * FIN + lane]      = dr * a0;
    g_ax[r * FIN + 32 + lane] = dr * a1;
}

// Fused: h1 = relu((A_n x) @ g1_W + g1_b) + (x @ res_W + res_b)
__global__ void k_fuse1(const float* __restrict__ x,
                        const float* __restrict__ g1W, const float* __restrict__ g1b,
                        const float* __restrict__ resW, const float* __restrict__ resb) {
    __shared__ float s_ax[FIN], s_x[FIN];
    int i = blockIdx.x, f = threadIdx.x;   // 128 threads
    if (f < FIN) { s_ax[f] = g_ax[i * FIN + f]; s_x[f] = x[i * FIN + f]; }
    __syncthreads();
    float acc = g1b[f], accR = resb[f];
    #pragma unroll
    for (int k = 0; k < FIN; k++) {
        acc  += s_ax[k] * g1W[k * HH + f];
        accR += s_x[k]  * resW[k * HH + f];
    }
    g_h1[i * HH + f] = fmaxf(acc, 0.f) + accR;
}

// SpMM layer 2: g_ah1 = A_n @ h1   (F = 128, warp per row, 4 feats/lane)
__global__ void k_spmm2() {
    int warp = (blockIdx.x * blockDim.x + threadIdx.x) >> 5;
    int lane = threadIdx.x & 31;
    if (warp >= NN) return;
    int r = warp;
    int cnt = min(g_cnt[r], CAP);
    float dr = g_dinv[r];
    float a0 = dr * g_h1[r * HH + lane];
    float a1 = dr * g_h1[r * HH + 32 + lane];
    float a2 = dr * g_h1[r * HH + 64 + lane];
    float a3 = dr * g_h1[r * HH + 96 + lane];
    for (int k = 0; k < cnt; k++) {
        int c = g_cols[r * CAP + k];
        float dc = g_dinv[c];
        const float* hc = &g_h1[c * HH];
        a0 += dc * hc[lane];
        a1 += dc * hc[32 + lane];
        a2 += dc * hc[64 + lane];
        a3 += dc * hc[96 + lane];
    }
    float* yo = &g_ah1[r * HH];
    yo[lane]      = dr * a0;
    yo[32 + lane] = dr * a1;
    yo[64 + lane] = dr * a2;
    yo[96 + lane] = dr * a3;
}

// Fused: h2 = relu((A_n h1) @ g2_W + g2_b), rowsum
__global__ void k_fuse2(const float* __restrict__ g2W, const float* __restrict__ g2b) {
    __shared__ float s_a[HH];
    __shared__ float s_p[4];
    int i = blockIdx.x, f = threadIdx.x;   // 128 threads
    s_a[f] = g_ah1[i * HH + f];
    __syncthreads();
    float acc = g2b[f];
    #pragma unroll
    for (int k = 0; k < HH; k++) acc += s_a[k] * g2W[k * HH + f];
    float h = fmaxf(acc, 0.f);
    g_h2[i * HH + f] = h;
    float v = h;
    #pragma unroll
    for (int o = 16; o > 0; o >>= 1) v += __shfl_down_sync(0xffffffffu, v, o);
    if ((f & 31) == 0) s_p[f >> 5] = v;
    __syncthreads();
    if (f == 0) g_rowsum[i] = s_p[0] + s_p[1] + s_p[2] + s_p[3];
}

// Pool softmax reduction over 8192 rowsums: store max & sumexp; zero g_graph
__global__ void k_poolred() {
    __shared__ float sm[32];
    __shared__ float s_max;
    int t = threadIdx.x;
    float m = -1e30f;
    for (int i = t; i < NN; i += 1024) m = fmaxf(m, g_rowsum[i]);
    #pragma unroll
    for (int o = 16; o > 0; o >>= 1) m = fmaxf(m, __shfl_down_sync(0xffffffffu, m, o));
    if ((t & 31) == 0) sm[t >> 5] = m;
    __syncthreads();
    if (t < 32) {
        float x = sm[t];
        #pragma unroll
        for (int o = 16; o > 0; o >>= 1) x = fmaxf(x, __shfl_down_sync(0xffffffffu, x, o));
        if (t == 0) s_max = x;
    }
    __syncthreads();
    float bm = s_max;
    float s = 0.f;
    for (int i = t; i < NN; i += 1024) s += expf(g_rowsum[i] - bm);
    #pragma unroll
    for (int o = 16; o > 0; o >>= 1) s += __shfl_down_sync(0xffffffffu, s, o);
    __syncthreads();               // before reusing sm
    if ((t & 31) == 0) sm[t >> 5] = s;
    __syncthreads();
    if (t < 32) {
        float x = sm[t];
        #pragma unroll
        for (int o = 16; o > 0; o >>= 1) x += __shfl_down_sync(0xffffffffu, x, o);
        if (t == 0) { g_red[0] = bm; g_red[1] = x; }
    }
    if (t < HH) g_graph[t] = 0.f;
}

// graph[f] += sum over a 64-row slab of imp_i * h2[i][f]
__global__ void k_poolw() {
    __shared__ float s_w[64];
    int f = threadIdx.x;           // 128 threads
    int r0 = blockIdx.x * 64;      // 128 blocks
    if (f < 64) s_w[f] = expf(g_rowsum[r0 + f] - g_red[0]) * (1.0f / g_red[1]);
    __syncthreads();
    float acc = 0.f;
    #pragma unroll 4
    for (int j = 0; j < 64; j++) acc += s_w[j] * g_h2[(r0 + j) * HH + f];
    atomicAdd(&g_graph[f], acc);
}

// Heads: actor hidden, critic (LayerNorm -> MLP -> value)
__global__ void k_head(const float* __restrict__ a1W, const float* __restrict__ a1b,
                       const float* __restrict__ lng, const float* __restrict__ lnb,
                       const float* __restrict__ c1W, const float* __restrict__ c1b,
                       const float* __restrict__ c2W, const float* __restrict__ c2b,
                       float* __restrict__ out, int out_size) {
    __shared__ float s_g[HH], s_z[HH], s_c[64];
    __shared__ float sm[4];
    int t = threadIdx.x;           // 128 threads
    s_g[t] = g_graph[t];
    __syncthreads();
    if (t < 64) {
        float a = a1b[t];
        #pragma unroll 8
        for (int k = 0; k < HH; k++) a += s_g[k] * a1W[k * 64 + t];
        g_af[t] = fmaxf(a, 0.f);
    }
    // LayerNorm mean
    float v = s_g[t];
    #pragma unroll
    for (int o = 16; o > 0; o >>= 1) v += __shfl_down_sync(0xffffffffu, v, o);
    if ((t & 31) == 0) sm[t >> 5] = v;
    __syncthreads();
    float mu = (sm[0] + sm[1] + sm[2] + sm[3]) * (1.0f / HH);
    __syncthreads();
    float d = s_g[t] - mu;
    float v2 = d * d;
    #pragma unroll
    for (int o = 16; o > 0; o >>= 1) v2 += __shfl_down_sync(0xffffffffu, v2, o);
    if ((t & 31) == 0) sm[t >> 5] = v2;
    __syncthreads();
    float var = (sm[0] + sm[1] + sm[2] + sm[3]) * (1.0f / HH);
    s_z[t] = d / sqrtf(var + 1e-5f) * lng[t] + lnb[t];
    __syncthreads();
    if (t < 64) {
        float c = c1b[t];
        #pragma unroll 8
        for (int k = 0; k < HH; k++) c += s_z[k] * c1W[k * 64 + t];
        s_c[t] = fmaxf(c, 0.f);
    }
    __syncthreads();
    if (t == 0) {
        float val = c2b[0];
        #pragma unroll 8
        for (int j = 0; j < 64; j++) val += s_c[j] * c2W[j];
        if (out_size > NN) out[NN] = val;
    }
}

// Actor logits: logits[o] = af @ a2_W[:,o] + a2_b[o]
__global__ void k_logits(const float* __restrict__ a2W, const float* __restrict__ a2b) {
    __shared__ float s_af[64];
    int t = threadIdx.x;           // 256 threads, 32 blocks
    if (t < 64) s_af[t] = g_af[t];
    __syncthreads();
    int o = blockIdx.x * blockDim.x + t;
    float acc = a2b[o];
    #pragma unroll
    for (int j = 0; j < 64; j++) acc += s_af[j] * a2W[j * AA + o];
    g_logits[o] = acc;
}

__global__ void k_lsm() {
    __shared__ float sm[32];
    __shared__ float s_max;
    int t = threadIdx.x;
    float m = -1e30f;
    for (int i = t; i < AA; i += 1024) m = fmaxf(m, g_logits[i]);
    #pragma unroll
    for (int o = 16; o > 0; o >>= 1) m = fmaxf(m, __shfl_down_sync(0xffffffffu, m, o));
    if ((t & 31) == 0) sm[t >> 5] = m;
    __syncthreads();
    if (t < 32) {
        float x = sm[t];
        #pragma unroll
        for (int o = 16; o > 0; o >>= 1) x = fmaxf(x, __shfl_down_sync(0xffffffffu, x, o));
        if (t == 0) s_max = x;
    }
    __syncthreads();
    float bm = s_max;
    float s = 0.f;
    for (int i = t; i < AA; i += 1024) s += expf(g_logits[i] - bm);
    #pragma unroll
    for (int o = 16; o > 0; o >>= 1) s += __shfl_down_sync(0xffffffffu, s, o);
    __syncthreads();
    if ((t & 31) == 0) sm[t >> 5] = s;
    __syncthreads();
    if (t < 32) {
        float x = sm[t];
        #pragma unroll
        for (int o = 16; o > 0; o >>= 1) x += __shfl_down_sync(0xffffffffu, x, o);
        if (t == 0) { g_red[2] = bm; g_red[3] = 1.0f / x; }
    }
}

__global__ void k_final(float* __restrict__ out) {
    int o = blockIdx.x * blockDim.x + threadIdx.x;
    if (o < AA) out[o] = expf(g_logits[o] - g_red[2]) * g_red[3];
}

// ---------------- launch ----------------
extern "C" void kernel_launch(void* const* d_in, const int* in_sizes, int n_in,
                              void* d_out, int out_size) {
    const float* x    = (const float*)d_in[0];
    const int*   ei   = (const int*)  d_in[1];
    int E = in_sizes[1] / 2;
    const float* g1W  = (const float*)d_in[2];
    const float* g1b  = (const float*)d_in[3];
    const float* g2W  = (const float*)d_in[4];
    const float* g2b  = (const float*)d_in[5];
    const float* resW = (const float*)d_in[6];
    const float* resb = (const float*)d_in[7];
    const float* a1W  = (const float*)d_in[8];
    const float* a1b  = (const float*)d_in[9];
    const float* a2W  = (const float*)d_in[10];
    const float* a2b  = (const float*)d_in[11];
    const float* lng  = (const float*)d_in[12];
    const float* lnb  = (const float*)d_in[13];
    const float* c1W  = (const float*)d_in[14];
    const float* c1b  = (const float*)d_in[15];
    const float* c2W  = (const float*)d_in[16];
    const float* c2b  = (const float*)d_in[17];
    float* out = (float*)d_out;

    k_detect<<<1, 32>>>(ei);
    k_clear<<<1024, 512>>>();
    k_dedup<<<(E + 255) / 256, 256>>>(ei, E);
    k_dinv<<<NN / 256, 256>>>();
    k_spmm1<<<(NN * 32) / 128, 128>>>(x);
    k_fuse1<<<NN, 128>>>(x, g1W, g1b, resW, resb);
    k_spmm2<<<(NN * 32) / 128, 128>>>();
    k_fuse2<<<NN, 128>>>(g2W, g2b);
    k_poolred<<<1, 1024>>>();
    k_poolw<<<128, 128>>>();
    k_head<<<1, 128>>>(a1W, a1b, lng, lnb, c1W, c1b, c2W, c2b, out, out_size);
    k_logits<<<AA / 256, 256>>>(a2W, a2b);
    k_lsm<<<1, 1024>>>();
    k_final<<<AA / 256, 256>>>(out);
}

// round 2
// speedup vs baseline: 1.0175x; 1.0175x over previous
#include <cuda_runtime.h>
#include <math.h>

#define NN   8192     // nodes
#define FIN  64       // input features
#define HH   128      // hidden
#define AA   8192     // action size
#define CAP  128      // max unique out-degree bucket capacity

// ---------------- device scratch (static, no allocations) ----------------
static __device__ unsigned g_bitmap[NN * (NN / 32)];   // 8 MB dedup bitmap
static __device__ int      g_cnt[NN];                  // unique out-degree
static __device__ int      g_cols[NN * CAP];           // bucketed CSR cols (4 MB)
static __device__ float    g_h1 [NN * HH];             // layer-1 output
static __device__ float    g_h2 [NN * HH];             // layer-2 output
static __device__ float    g_rowsum[NN];
static __device__ float    g_graph[HH];
static __device__ float    g_af[64];                   // actor hidden
static __device__ float    g_logits[AA];
static __device__ float    g_red[4];                   // pool max, pool sumexp, logit max, logit 1/sum
static __device__ int      g_is64;
static __device__ int      g_ctr0, g_ctr1, g_ctr2;     // last-block counters

// ---------------- kernels ----------------

// Init: clear bitmap/cnt/graph/counters; detect int64 vs int32 edge layout
__global__ void k_init(const int* __restrict__ e) {
    const int total4 = (NN * (NN / 32)) / 4;   // uint4 count
    uint4* bm = reinterpret_cast<uint4*>(g_bitmap);
    int i = blockIdx.x * blockDim.x + threadIdx.x;
    int stride = gridDim.x * blockDim.x;
    uint4 z = make_uint4(0u, 0u, 0u, 0u);
    for (int w = i; w < total4; w += stride) bm[w] = z;
    if (i < NN) g_cnt[i] = 0;
    if (i < HH) g_graph[i] = 0.f;
    if (i == 0) {
        g_ctr0 = 0; g_ctr1 = 0; g_ctr2 = 0;
        int all0 = 1;
        #pragma unroll
        for (int k = 0; k < 32; k++)
            if (e[2 * k + 1] != 0) all0 = 0;
        g_is64 = all0;
    }
}

__global__ void k_dedup(const int* __restrict__ e, int E) {
    int idx = blockIdx.x * blockDim.x + threadIdx.x;
    if (idx >= E) return;
    int r, c;
    if (g_is64) { r = e[2 * idx]; c = e[2 * (E + idx)]; }
    else        { r = e[idx];     c = e[E + idx]; }
    unsigned lin = (unsigned)r * NN + (unsigned)c;   // < 2^26
    unsigned w = lin >> 5, b = lin & 31u;
    unsigned old = atomicOr(&g_bitmap[w], 1u << b);
    if (!((old >> b) & 1u)) {
        int pos = atomicAdd(&g_cnt[r], 1);
        if (pos < CAP) g_cols[r * CAP + pos] = c;
    }
}

// Fused layer 1: per row i, gather A_n x into smem, then
// h1 = relu(ax @ g1_W + g1_b) + (x @ res_W + res_b)
__global__ void __launch_bounds__(128) k_l1(const float* __restrict__ x,
                      const float* __restrict__ g1W, const float* __restrict__ g1b,
                      const float* __restrict__ resW, const float* __restrict__ resb) {
    __shared__ int   s_cols[CAP];
    __shared__ float s_dinv[CAP];
    __shared__ float s_x[FIN];
    __shared__ float s_ax[FIN];
    __shared__ float s_part[128];
    int i = blockIdx.x, t = threadIdx.x;   // 128 threads
    int cnt = min(g_cnt[i], CAP);
    float dr = rsqrtf((float)(cnt + 1));
    if (t < cnt) {
        int c = g_cols[i * CAP + t];
        s_cols[t] = c;
        s_dinv[t] = rsqrtf((float)(min(g_cnt[c], CAP) + 1));
    }
    if (t < FIN) s_x[t] = x[i * FIN + t];
    __syncthreads();
    // gather: 2 threads per feature, even/odd neighbor split
    {
        int f = t & 63, half = t >> 6;
        float p = 0.f;
        #pragma unroll 4
        for (int k = half; k < cnt; k += 2)
            p += s_dinv[k] * x[s_cols[k] * FIN + f];
        s_part[t] = p;
    }
    __syncthreads();
    if (t < FIN)
        s_ax[t] = dr * (dr * s_x[t] + s_part[t] + s_part[t + 64]);
    __syncthreads();
    float acc = g1b[t], accR = resb[t];
    #pragma unroll 16
    for (int k = 0; k < FIN; k++) {
        acc  += s_ax[k] * g1W[k * HH + t];
        accR += s_x[k]  * resW[k * HH + t];
    }
    g_h1[i * HH + t] = fmaxf(acc, 0.f) + accR;
}

// Fused layer 2: per row, gather A_n h1, GEMV+relu, rowsum.
// Last block: pooling-softmax reduction over rowsums.
__global__ void __launch_bounds__(128) k_l2(const float* __restrict__ g2W, const float* __restrict__ g2b) {
    __shared__ int   s_cols[CAP];
    __shared__ float s_dinv[CAP];
    __shared__ float s_h[HH];
    __shared__ float s_a[HH];
    __shared__ float s_m[4];
    __shared__ float s_bm;
    __shared__ int   s_last;
    int i = blockIdx.x, t = threadIdx.x;   // 128 threads
    int cnt = min(g_cnt[i], CAP);
    float dr = rsqrtf((float)(cnt + 1));
    if (t < cnt) {
        int c = g_cols[i * CAP + t];
        s_cols[t] = c;
        s_dinv[t] = rsqrtf((float)(min(g_cnt[c], CAP) + 1));
    }
    s_h[t] = g_h1[i * HH + t];
    __syncthreads();
    float a = dr * s_h[t];
    #pragma unroll 4
    for (int k = 0; k < cnt; k++)
        a += s_dinv[k] * g_h1[s_cols[k] * HH + t];
    s_a[t] = dr * a;
    __syncthreads();
    float acc = g2b[t];
    #pragma unroll 16
    for (int k = 0; k < HH; k++) acc += s_a[k] * g2W[k * HH + t];
    float h = fmaxf(acc, 0.f);
    g_h2[i * HH + t] = h;
    float v = h;
    #pragma unroll
    for (int o = 16; o > 0; o >>= 1) v += __shfl_down_sync(0xffffffffu, v, o);
    if ((t & 31) == 0) s_m[t >> 5] = v;
    __syncthreads();
    if (t == 0) g_rowsum[i] = s_m[0] + s_m[1] + s_m[2] + s_m[3];

    // ---- last-block pooling-softmax reduction ----
    __threadfence();
    if (t == 0) {
        int done = atomicAdd(&g_ctr0, 1);
        s_last = (done == (int)gridDim.x - 1);
    }
    __syncthreads();
    if (!s_last) return;
    // 128 threads reduce max over 8192 rowsums
    float m = -1e30f;
    for (int j = t; j < NN; j += 128) m = fmaxf(m, g_rowsum[j]);
    #pragma unroll
    for (int o = 16; o > 0; o >>= 1) m = fmaxf(m, __shfl_down_sync(0xffffffffu, m, o));
    if ((t & 31) == 0) s_m[t >> 5] = m;
    __syncthreads();
    if (t == 0) s_bm = fmaxf(fmaxf(s_m[0], s_m[1]), fmaxf(s_m[2], s_m[3]));
    __syncthreads();
    float bm = s_bm;
    float s = 0.f;
    for (int j = t; j < NN; j += 128) s += expf(g_rowsum[j] - bm);
    #pragma unroll
    for (int o = 16; o > 0; o >>= 1) s += __shfl_down_sync(0xffffffffu, s, o);
    __syncthreads();
    if ((t & 31) == 0) s_m[t >> 5] = s;
    __syncthreads();
    if (t == 0) {
        g_red[0] = bm;
        g_red[1] = s_m[0] + s_m[1] + s_m[2] + s_m[3];
        g_ctr0 = 0;
    }
}

// Pool: graph[f] += sum over 64-row slab of imp_i * h2[i][f].
// Last block: actor hidden + critic (LayerNorm -> MLP -> value).
__global__ void __launch_bounds__(128) k_pool(const float* __restrict__ a1W, const float* __restrict__ a1b,
                        const float* __restrict__ lng, const float* __restrict__ lnb,
                        const float* __restrict__ c1W, const float* __restrict__ c1b,
                        const float* __restrict__ c2W, const float* __restrict__ c2b,
                        float* __restrict__ out, int out_size) {
    __shared__ float s_w[64];
    __shared__ float s_g[HH], s_z[HH], s_c[64];
    __shared__ float sm[4];
    __shared__ int   s_last;
    int t = threadIdx.x;           // 128 threads
    int r0 = blockIdx.x * 64;      // 128 blocks
    if (t < 64) s_w[t] = expf(g_rowsum[r0 + t] - g_red[0]) * (1.0f / g_red[1]);
    __syncthreads();
    float acc = 0.f;
    #pragma unroll 4
    for (int j = 0; j < 64; j++) acc += s_w[j] * g_h2[(r0 + j) * HH + t];
    atomicAdd(&g_graph[t], acc);

    __threadfence();
    if (t == 0) {
        int done = atomicAdd(&g_ctr1, 1);
        s_last = (done == (int)gridDim.x - 1);
    }
    __syncthreads();
    if (!s_last) return;

    s_g[t] = g_graph[t];
    __syncthreads();
    if (t < 64) {
        float a = a1b[t];
        #pragma unroll 8
        for (int k = 0; k < HH; k++) a += s_g[k] * a1W[k * 64 + t];
        g_af[t] = fmaxf(a, 0.f);
    }
    // LayerNorm mean
    float v = s_g[t];
    #pragma unroll
    for (int o = 16; o > 0; o >>= 1) v += __shfl_down_sync(0xffffffffu, v, o);
    if ((t & 31) == 0) sm[t >> 5] = v;
    __syncthreads();
    float mu = (sm[0] + sm[1] + sm[2] + sm[3]) * (1.0f / HH);
    __syncthreads();
    float d = s_g[t] - mu;
    float v2 = d * d;
    #pragma unroll
    for (int o = 16; o > 0; o >>= 1) v2 += __shfl_down_sync(0xffffffffu, v2, o);
    if ((t & 31) == 0) sm[t >> 5] = v2;
    __syncthreads();
    float var = (sm[0] + sm[1] + sm[2] + sm[3]) * (1.0f / HH);
    s_z[t] = d / sqrtf(var + 1e-5f) * lng[t] + lnb[t];
    __syncthreads();
    if (t < 64) {
        float c = c1b[t];
        #pragma unroll 8
        for (int k = 0; k < HH; k++) c += s_z[k] * c1W[k * 64 + t];
        s_c[t] = fmaxf(c, 0.f);
    }
    __syncthreads();
    if (t == 0) {
        float val = c2b[0];
        #pragma unroll 8
        for (int j = 0; j < 64; j++) val += s_c[j] * c2W[j];
        if (out_size > NN) out[NN] = val;
        g_ctr1 = 0;
    }
}

// Actor logits; last block computes softmax stats and writes action probs.
__global__ void __launch_bounds__(256) k_act(const float* __restrict__ a2W, const float* __restrict__ a2b,
                       float* __restrict__ out) {
    __shared__ float s_af[64];
    __shared__ float sm[8];
    __shared__ float s_bm;
    __shared__ int   s_last;
    int t = threadIdx.x;           // 256 threads, 32 blocks
    if (t < 64) s_af[t] = g_af[t];
    __syncthreads();
    int o = blockIdx.x * 256 + t;
    float acc = a2b[o];
    #pragma unroll
    for (int j = 0; j < 64; j++) acc += s_af[j] * a2W[j * AA + o];
    g_logits[o] = acc;

    __threadfence();
    if (t == 0) {
        int done = atomicAdd(&g_ctr2, 1);
        s_last = (done == (int)gridDim.x - 1);
    }
    __syncthreads();
    if (!s_last) return;

    float m = -1e30f;
    for (int j = t; j < AA; j += 256) m = fmaxf(m, g_logits[j]);
    #pragma unroll
    for (int ofs = 16; ofs > 0; ofs >>= 1) m = fmaxf(m, __shfl_down_sync(0xffffffffu, m, ofs));
    if ((t & 31) == 0) sm[t >> 5] = m;
    __syncthreads();
    if (t == 0) {
        float x = sm[0];
        #pragma unroll
        for (int j = 1; j < 8; j++) x = fmaxf(x, sm[j]);
        s_bm = x;
    }
    __syncthreads();
    float bm = s_bm;
    float s = 0.f;
    for (int j = t; j < AA; j += 256) s += expf(g_logits[j] - bm);
    #pragma unroll
    for (int ofs = 16; ofs > 0; ofs >>= 1) s += __shfl_down_sync(0xffffffffu, s, ofs);
    __syncthreads();
    if ((t & 31) == 0) sm[t >> 5] = s;
    __syncthreads();
    if (t == 0) {
        float x = 0.f;
        #pragma unroll
        for (int j = 0; j < 8; j++) x += sm[j];
        s_bm = 1.0f / x;   // reuse as inv-sum
        g_ctr2 = 0;
    }
    __syncthreads();
    float inv = s_bm;
    for (int j = t; j < AA; j += 256) out[j] = expf(g_logits[j] - bm) * inv;
}

// ---------------- launch ----------------
extern "C" void kernel_launch(void* const* d_in, const int* in_sizes, int n_in,
                              void* d_out, int out_size) {
    const float* x    = (const float*)d_in[0];
    const int*   ei   = (const int*)  d_in[1];
    int E = in_sizes[1] / 2;
    const float* g1W  = (const float*)d_in[2];
    const float* g1b  = (const float*)d_in[3];
    const float* g2W  = (const float*)d_in[4];
    const float* g2b  = (const float*)d_in[5];
    const float* resW = (const float*)d_in[6];
    const float* resb = (const float*)d_in[7];
    const float* a1W  = (const float*)d_in[8];
    const float* a1b  = (const float*)d_in[9];
    const float* a2W  = (const float*)d_in[10];
    const float* a2b  = (const float*)d_in[11];
    const float* lng  = (const float*)d_in[12];
    const float* lnb  = (const float*)d_in[13];
    const float* c1W  = (const float*)d_in[14];
    const float* c1b  = (const float*)d_in[15];
    const float* c2W  = (const float*)d_in[16];
    const float* c2b  = (const float*)d_in[17];
    float* out = (float*)d_out;

    k_init <<<1024, 512>>>(ei);
    k_dedup<<<(E + 255) / 256, 256>>>(ei, E);
    k_l1   <<<NN, 128>>>(x, g1W, g1b, resW, resb);
    k_l2   <<<NN, 128>>>(g2W, g2b);
    k_pool <<<128, 128>>>(a1W, a1b, lng, lnb, c1W, c1b, c2W, c2b, out, out_size);
    k_act  <<<32, 256>>>(a2W, a2b, out);
}

// round 3
// speedup vs baseline: 1.0926x; 1.0738x over previous
#include <cuda_runtime.h>
#include <math.h>

#define NN   8192     // nodes
#define FIN  64       // input features
#define HH   128      // hidden
#define AA   8192     // action size
#define CAP  128      // max unique out-degree bucket capacity
#define RB   16       // rows per GEMM block

// ---------------- device scratch (static, no allocations) ----------------
static __device__ unsigned g_bitmap[NN * (NN / 32)];   // 8 MB dedup bitmap
static __device__ int      g_cnt[NN];                  // unique out-degree
static __device__ int      g_cols[NN * CAP];           // bucketed CSR cols (4 MB)
static __device__ float    g_P [NN * HH];              // x @ g1W
static __device__ float    g_R [NN * HH];              // x @ resW + resb
static __device__ float    g_h1[NN * HH];              // layer-1 output
static __device__ float    g_Q [NN * HH];              // h1 @ g2W
static __device__ float    g_h2[NN * HH];              // layer-2 output
static __device__ float    g_rowsum[NN];
static __device__ float    g_graph[HH];
static __device__ float    g_af[64];                   // actor hidden
static __device__ float    g_logits[AA];
static __device__ float    g_red[2];                   // pool max, pool sumexp
static __device__ int      g_is64;
static __device__ int      g_ctr0, g_ctr1, g_ctr2;     // last-block counters

// ---------------- kernels ----------------

// Init: clear bitmap/cnt/graph/counters; detect int64 vs int32 edge layout
__global__ void k_init(const int* __restrict__ e) {
    const int total4 = (NN * (NN / 32)) / 4;   // uint4 count
    uint4* bm = reinterpret_cast<uint4*>(g_bitmap);
    int i = blockIdx.x * blockDim.x + threadIdx.x;
    int stride = gridDim.x * blockDim.x;
    uint4 z = make_uint4(0u, 0u, 0u, 0u);
    for (int w = i; w < total4; w += stride) bm[w] = z;
    if (i < NN) g_cnt[i] = 0;
    if (i < HH) g_graph[i] = 0.f;
    if (i == 0) {
        g_ctr0 = 0; g_ctr1 = 0; g_ctr2 = 0;
        int all0 = 1;
        #pragma unroll
        for (int k = 0; k < 32; k++)
            if (e[2 * k + 1] != 0) all0 = 0;
        g_is64 = all0;
    }
}

__global__ void k_dedup(const int* __restrict__ e, int E) {
    int idx = blockIdx.x * blockDim.x + threadIdx.x;
    if (idx >= E) return;
    int r, c;
    if (g_is64) { r = e[2 * idx]; c = e[2 * (E + idx)]; }
    else        { r = e[idx];     c = e[E + idx]; }
    unsigned lin = (unsigned)r * NN + (unsigned)c;   // < 2^26
    unsigned w = lin >> 5, b = lin & 31u;
    unsigned old = atomicOr(&g_bitmap[w], 1u << b);
    if (!((old >> b) & 1u)) {
        int pos = atomicAdd(&g_cnt[r], 1);
        if (pos < CAP) g_cols[r * CAP + pos] = c;
    }
}

// GEMM1: P = x @ g1W ; R = x @ resW + resb. 256 threads, 16 rows/block.
__global__ void __launch_bounds__(256) k_gemm1(const float* __restrict__ x,
                        const float* __restrict__ g1W,
                        const float* __restrict__ resW, const float* __restrict__ resb) {
    __shared__ float s_x[FIN * RB];          // [k][r]
    int r0 = blockIdx.x * RB;
    int t = threadIdx.x;
    for (int u = t; u < FIN * RB; u += 256) {
        int r = u >> 6, k = u & 63;
        s_x[k * RB + r] = x[(r0 + r) * FIN + k];
    }
    __syncthreads();
    const float* W = (t < HH) ? g1W : resW;
    int col = t & (HH - 1);
    float acc[RB];
    #pragma unroll
    for (int r = 0; r < RB; r++) acc[r] = 0.f;
    #pragma unroll 4
    for (int k = 0; k < FIN; k++) {
        float w = W[k * HH + col];
        const float4* xv = reinterpret_cast<const float4*>(&s_x[k * RB]);
        #pragma unroll
        for (int rr = 0; rr < RB / 4; rr++) {
            float4 v = xv[rr];
            acc[rr * 4 + 0] += v.x * w;
            acc[rr * 4 + 1] += v.y * w;
            acc[rr * 4 + 2] += v.z * w;
            acc[rr * 4 + 3] += v.w * w;
        }
    }
    if (t < HH) {
        #pragma unroll
        for (int r = 0; r < RB; r++) g_P[(r0 + r) * HH + col] = acc[r];
    } else {
        float b = resb[col];
        #pragma unroll
        for (int r = 0; r < RB; r++) g_R[(r0 + r) * HH + col] = acc[r] + b;
    }
}

// SpMM1: h1 = relu(A_n P + g1b) + R. Block per row, 128 threads.
__global__ void __launch_bounds__(128) k_spmm1(const float* __restrict__ g1b) {
    __shared__ int   s_cols[CAP];
    __shared__ float s_dinv[CAP];
    int i = blockIdx.x, t = threadIdx.x;
    int cnt = min(g_cnt[i], CAP);
    if (t < cnt) {
        int c = g_cols[i * CAP + t];
        s_cols[t] = c;
        s_dinv[t] = rsqrtf((float)(min(g_cnt[c], CAP) + 1));
    }
    __syncthreads();
    float dr = rsqrtf((float)(cnt + 1));
    float acc = dr * g_P[i * HH + t];
    #pragma unroll 4
    for (int k = 0; k < cnt; k++)
        acc += s_dinv[k] * g_P[s_cols[k] * HH + t];
    g_h1[i * HH + t] = fmaxf(dr * acc + g1b[t], 0.f) + g_R[i * HH + t];
}

// GEMM2: Q = h1 @ g2W. 128 threads, 16 rows/block.
__global__ void __launch_bounds__(128) k_gemm2(const float* __restrict__ g2W) {
    __shared__ float s_h[HH * RB];           // [k][r]
    int r0 = blockIdx.x * RB;
    int t = threadIdx.x;
    for (int u = t; u < HH * RB; u += 128) {
        int r = u >> 7, k = u & 127;
        s_h[k * RB + r] = g_h1[(r0 + r) * HH + k];
    }
    __syncthreads();
    float acc[RB];
    #pragma unroll
    for (int r = 0; r < RB; r++) acc[r] = 0.f;
    #pragma unroll 4
    for (int k = 0; k < HH; k++) {
        float w = g2W[k * HH + t];
        const float4* hv = reinterpret_cast<const float4*>(&s_h[k * RB]);
        #pragma unroll
        for (int rr = 0; rr < RB / 4; rr++) {
            float4 v = hv[rr];
            acc[rr * 4 + 0] += v.x * w;
            acc[rr * 4 + 1] += v.y * w;
            acc[rr * 4 + 2] += v.z * w;
            acc[rr * 4 + 3] += v.w * w;
        }
    }
    #pragma unroll
    for (int r = 0; r < RB; r++) g_Q[(r0 + r) * HH + t] = acc[r];
}

// SpMM2: h2 = relu(A_n Q + g2b), rowsum; last block: pooling softmax stats.
__global__ void __launch_bounds__(128) k_spmm2(const float* __restrict__ g2b) {
    __shared__ int   s_cols[CAP];
    __shared__ float s_dinv[CAP];
    __shared__ float s_m[4];
    __shared__ float s_bm;
    __shared__ int   s_last;
    int i = blockIdx.x, t = threadIdx.x;
    int cnt = min(g_cnt[i], CAP);
    if (t < cnt) {
        int c = g_cols[i * CAP + t];
        s_cols[t] = c;
        s_dinv[t] = rsqrtf((float)(min(g_cnt[c], CAP) + 1));
    }
    __syncthreads();
    float dr = rsqrtf((float)(cnt + 1));
    float acc = dr * g_Q[i * HH + t];
    #pragma unroll 4
    for (int k = 0; k < cnt; k++)
        acc += s_dinv[k] * g_Q[s_cols[k] * HH + t];
    float h = fmaxf(dr * acc + g2b[t], 0.f);
    g_h2[i * HH + t] = h;
    float v = h;
    #pragma unroll
    for (int o = 16; o > 0; o >>= 1) v += __shfl_down_sync(0xffffffffu, v, o);
    if ((t & 31) == 0) s_m[t >> 5] = v;
    __syncthreads();
    if (t == 0) g_rowsum[i] = s_m[0] + s_m[1] + s_m[2] + s_m[3];

    __threadfence();
    if (t == 0) {
        int done = atomicAdd(&g_ctr0, 1);
        s_last = (done == (int)gridDim.x - 1);
    }
    __syncthreads();
    if (!s_last) return;
    float m = -1e30f;
    for (int j = t; j < NN; j += 128) m = fmaxf(m, g_rowsum[j]);
    #pragma unroll
    for (int o = 16; o > 0; o >>= 1) m = fmaxf(m, __shfl_down_sync(0xffffffffu, m, o));
    if ((t & 31) == 0) s_m[t >> 5] = m;
    __syncthreads();
    if (t == 0) s_bm = fmaxf(fmaxf(s_m[0], s_m[1]), fmaxf(s_m[2], s_m[3]));
    __syncthreads();
    float bm = s_bm;
    float s = 0.f;
    for (int j = t; j < NN; j += 128) s += expf(g_rowsum[j] - bm);
    #pragma unroll
    for (int o = 16; o > 0; o >>= 1) s += __shfl_down_sync(0xffffffffu, s, o);
    __syncthreads();
    if ((t & 31) == 0) s_m[t >> 5] = s;
    __syncthreads();
    if (t == 0) {
        g_red[0] = bm;
        g_red[1] = s_m[0] + s_m[1] + s_m[2] + s_m[3];
        g_ctr0 = 0;
    }
}

// Pool + (last block) heads.
__global__ void __launch_bounds__(128) k_pool(const float* __restrict__ a1W, const float* __restrict__ a1b,
                        const float* __restrict__ lng, const float* __restrict__ lnb,
                        const float* __restrict__ c1W, const float* __restrict__ c1b,
                        const float* __restrict__ c2W, const float* __restrict__ c2b,
                        float* __restrict__ out, int out_size) {
    __shared__ float s_w[64];
    __shared__ float s_g[HH], s_z[HH], s_c[64];
    __shared__ float sm[4];
    __shared__ int   s_last;
    int t = threadIdx.x;           // 128 threads
    int r0 = blockIdx.x * 64;      // 128 blocks
    if (t < 64) s_w[t] = expf(g_rowsum[r0 + t] - g_red[0]) * (1.0f / g_red[1]);
    __syncthreads();
    float acc = 0.f;
    #pragma unroll 4
    for (int j = 0; j < 64; j++) acc += s_w[j] * g_h2[(r0 + j) * HH + t];
    atomicAdd(&g_graph[t], acc);

    __threadfence();
    if (t == 0) {
        int done = atomicAdd(&g_ctr1, 1);
        s_last = (done == (int)gridDim.x - 1);
    }
    __syncthreads();
    if (!s_last) return;

    s_g[t] = g_graph[t];
    __syncthreads();
    if (t < 64) {
        float a = a1b[t];
        #pragma unroll 8
        for (int k = 0; k < HH; k++) a += s_g[k] * a1W[k * 64 + t];
        g_af[t] = fmaxf(a, 0.f);
    }
    float v = s_g[t];
    #pragma unroll
    for (int o = 16; o > 0; o >>= 1) v += __shfl_down_sync(0xffffffffu, v, o);
    if ((t & 31) == 0) sm[t >> 5] = v;
    __syncthreads();
    float mu = (sm[0] + sm[1] + sm[2] + sm[3]) * (1.0f / HH);
    __syncthreads();
    float d = s_g[t] - mu;
    float v2 = d * d;
    #pragma unroll
    for (int o = 16; o > 0; o >>= 1) v2 += __shfl_down_sync(0xffffffffu, v2, o);
    if ((t & 31) == 0) sm[t >> 5] = v2;
    __syncthreads();
    float var = (sm[0] + sm[1] + sm[2] + sm[3]) * (1.0f / HH);
    s_z[t] = d / sqrtf(var + 1e-5f) * lng[t] + lnb[t];
    __syncthreads();
    if (t < 64) {
        float c = c1b[t];
        #pragma unroll 8
        for (int k = 0; k < HH; k++) c += s_z[k] * c1W[k * 64 + t];
        s_c[t] = fmaxf(c, 0.f);
    }
    __syncthreads();
    if (t == 0) {
        float val = c2b[0];
        #pragma unroll 8
        for (int j = 0; j < 64; j++) val += s_c[j] * c2W[j];
        if (out_size > NN) out[NN] = val;
        g_ctr1 = 0;
    }
}

// Actor logits; last block computes softmax and writes action probs.
__global__ void __launch_bounds__(256) k_act(const float* __restrict__ a2W, const float* __restrict__ a2b,
                       float* __restrict__ out) {
    __shared__ float s_af[64];
    __shared__ float sm[8];
    __shared__ float s_bm;
    __shared__ int   s_last;
    int t = threadIdx.x;           // 256 threads, 32 blocks
    if (t < 64) s_af[t] = g_af[t];
    __syncthreads();
    int o = blockIdx.x * 256 + t;
    float acc = a2b[o];
    #pragma unroll
    for (int j = 0; j < 64; j++) acc += s_af[j] * a2W[j * AA + o];
    g_logits[o] = acc;

    __threadfence();
    if (t == 0) {
        int done = atomicAdd(&g_ctr2, 1);
        s_last = (done == (int)gridDim.x - 1);
    }
    __syncthreads();
    if (!s_last) return;

    float m = -1e30f;
    for (int j = t; j < AA; j += 256) m = fmaxf(m, g_logits[j]);
    #pragma unroll
    for (int ofs = 16; ofs > 0; ofs >>= 1) m = fmaxf(m, __shfl_down_sync(0xffffffffu, m, ofs));
    if ((t & 31) == 0) sm[t >> 5] = m;
    __syncthreads();
    if (t == 0) {
        float x = sm[0];
        #pragma unroll
        for (int j = 1; j < 8; j++) x = fmaxf(x, sm[j]);
        s_bm = x;
    }
    __syncthreads();
    float bm = s_bm;
    float s = 0.f;
    for (int j = t; j < AA; j += 256) s += expf(g_logits[j] - bm);
    #pragma unroll
    for (int ofs = 16; ofs > 0; ofs >>= 1) s += __shfl_down_sync(0xffffffffu, s, ofs);
    __syncthreads();
    if ((t & 31) == 0) sm[t >> 5] = s;
    __syncthreads();
    if (t == 0) {
        float x = 0.f;
        #pragma unroll
        for (int j = 0; j < 8; j++) x += sm[j];
        s_bm = 1.0f / x;
        g_ctr2 = 0;
    }
    __syncthreads();
    float inv = s_bm;
    for (int j = t; j < AA; j += 256) out[j] = expf(g_logits[j] - bm) * inv;
}

// ---------------- launch ----------------
extern "C" void kernel_launch(void* const* d_in, const int* in_sizes, int n_in,
                              void* d_out, int out_size) {
    const float* x    = (const float*)d_in[0];
    const int*   ei   = (const int*)  d_in[1];
    int E = in_sizes[1] / 2;
    const float* g1W  = (const float*)d_in[2];
    const float* g1b  = (const float*)d_in[3];
    const float* g2W  = (const float*)d_in[4];
    const float* g2b  = (const float*)d_in[5];
    const float* resW = (const float*)d_in[6];
    const float* resb = (const float*)d_in[7];
    const float* a1W  = (const float*)d_in[8];
    const float* a1b  = (const float*)d_in[9];
    const float* a2W  = (const float*)d_in[10];
    const float* a2b  = (const float*)d_in[11];
    const float* lng  = (const float*)d_in[12];
    const float* lnb  = (const float*)d_in[13];
    const float* c1W  = (const float*)d_in[14];
    const float* c1b  = (const float*)d_in[15];
    const float* c2W  = (const float*)d_in[16];
    const float* c2b  = (const float*)d_in[17];
    float* out = (float*)d_out;

    k_init <<<1024, 512>>>(ei);
    k_dedup<<<(E + 255) / 256, 256>>>(ei, E);
    k_gemm1<<<NN / RB, 256>>>(x, g1W, resW, resb);
    k_spmm1<<<NN, 128>>>(g1b);
    k_gemm2<<<NN / RB, 128>>>(g2W);
    k_spmm2<<<NN, 128>>>(g2b);
    k_pool <<<128, 128>>>(a1W, a1b, lng, lnb, c1W, c1b, c2W, c2b, out, out_size);
    k_act  <<<32, 256>>>(a2W, a2b, out);
}

// round 4
// speedup vs baseline: 1.2360x; 1.1313x over previous
#include <cuda_runtime.h>
#include <math.h>

#define NN   8192     // nodes
#define FIN  64       // input features
#define HH   128      // hidden
#define AA   8192     // action size
#define CAP  128      // max unique out-degree bucket capacity
#define RB   16       // rows per GEMM block

// ---------------- device scratch (static, no allocations) ----------------
static __device__ unsigned g_bitmap[NN * (NN / 32)];   // 8 MB dedup bitmap
static __device__ int      g_cnt[NN];                  // unique out-degree
static __device__ int      g_cols[NN * CAP];           // bucketed CSR cols (4 MB)
static __device__ float    g_ax[NN * FIN];             // A_n @ x
static __device__ float    g_h1[NN * HH];              // layer-1 output
static __device__ float    g_Q [NN * HH];              // h1 @ g2W
static __device__ float    g_h2[NN * HH];              // layer-2 output
static __device__ float    g_rowsum[NN];
static __device__ float    g_graph[HH];
static __device__ float    g_af[64];                   // actor hidden
static __device__ float    g_logits[AA];
static __device__ float    g_red[2];                   // pool max, pool sumexp
static __device__ int      g_is64;
static __device__ int      g_ctr0, g_ctr1, g_ctr2;     // last-block counters

// ---------------- kernels ----------------

__global__ void k_init(const int* __restrict__ e) {
    const int total4 = (NN * (NN / 32)) / 4;
    uint4* bm = reinterpret_cast<uint4*>(g_bitmap);
    int i = blockIdx.x * blockDim.x + threadIdx.x;
    int stride = gridDim.x * blockDim.x;
    uint4 z = make_uint4(0u, 0u, 0u, 0u);
    for (int w = i; w < total4; w += stride) bm[w] = z;
    if (i < NN) g_cnt[i] = 0;
    if (i < HH) g_graph[i] = 0.f;
    if (i == 0) {
        g_ctr0 = 0; g_ctr1 = 0; g_ctr2 = 0;
        int all0 = 1;
        #pragma unroll
        for (int k = 0; k < 32; k++)
            if (e[2 * k + 1] != 0) all0 = 0;
        g_is64 = all0;
    }
}

__global__ void k_dedup(const int* __restrict__ e, int E) {
    int idx = blockIdx.x * blockDim.x + threadIdx.x;
    if (idx >= E) return;
    int r, c;
    if (g_is64) { r = e[2 * idx]; c = e[2 * (E + idx)]; }
    else        { r = e[idx];     c = e[E + idx]; }
    unsigned lin = (unsigned)r * NN + (unsigned)c;
    unsigned w = lin >> 5, b = lin & 31u;
    unsigned old = atomicOr(&g_bitmap[w], 1u << b);
    if (!((old >> b) & 1u)) {
        int pos = atomicAdd(&g_cnt[r], 1);
        if (pos < CAP) g_cols[r * CAP + pos] = c;
    }
}

// SpMM on input: ax = A_n @ x. Warp per row, float2 per lane (64 feats).
__global__ void __launch_bounds__(128) k_spmmx(const float* __restrict__ x) {
    __shared__ int   s_cols[4][CAP];
    __shared__ float s_dinv[4][CAP];
    int t = threadIdx.x, wid = t >> 5, lane = t & 31;
    int r = blockIdx.x * 4 + wid;
    int cnt = min(g_cnt[r], CAP);
    for (int k = lane; k < cnt; k += 32) {
        int c = g_cols[r * CAP + k];
        s_cols[wid][k] = c;
        s_dinv[wid][k] = rsqrtf((float)(min(g_cnt[c], CAP) + 1));
    }
    __syncwarp();
    float dr = rsqrtf((float)(cnt + 1));
    const float2* xv = reinterpret_cast<const float2*>(x);
    float2 self = xv[r * 32 + lane];
    float a0 = dr * self.x, a1 = dr * self.y;
    float b0 = 0.f, b1 = 0.f;
    int k = 0;
    #pragma unroll 2
    for (; k + 1 < cnt; k += 2) {
        int   c0 = s_cols[wid][k],   c1 = s_cols[wid][k + 1];
        float d0 = s_dinv[wid][k],   d1 = s_dinv[wid][k + 1];
        float2 v0 = xv[c0 * 32 + lane];
        float2 v1 = xv[c1 * 32 + lane];
        a0 += d0 * v0.x; a1 += d0 * v0.y;
        b0 += d1 * v1.x; b1 += d1 * v1.y;
    }
    if (k < cnt) {
        int c = s_cols[wid][k]; float d = s_dinv[wid][k];
        float2 v = xv[c * 32 + lane];
        a0 += d * v.x; a1 += d * v.y;
    }
    reinterpret_cast<float2*>(g_ax)[r * 32 + lane] =
        make_float2(dr * (a0 + b0), dr * (a1 + b1));
}

// Fused layer-1 GEMM: h1 = relu(ax@g1W + g1b) + (x@resW + resb).
// 256 threads: t<128 -> g1 column, t>=128 -> res column. 16 rows per block.
__global__ void __launch_bounds__(256) k_l1(const float* __restrict__ x,
                      const float* __restrict__ g1W, const float* __restrict__ g1b,
                      const float* __restrict__ resW, const float* __restrict__ resb) {
    __shared__ float s_ax[FIN * RB];     // [k][r]
    __shared__ float s_x [FIN * RB];
    __shared__ float s_res[RB * HH];
    int r0 = blockIdx.x * RB;
    int t = threadIdx.x;
    for (int u = t; u < FIN * RB; u += 256) {
        int r = u >> 6, k = u & 63;
        s_ax[k * RB + r] = g_ax[(r0 + r) * FIN + k];
        s_x [k * RB + r] = x[(r0 + r) * FIN + k];
    }
    __syncthreads();
    int col = t & 127;
    bool isG = t < 128;
    const float* W = isG ? g1W : resW;
    const float* S = isG ? s_ax : s_x;
    float acc[RB];
    #pragma unroll
    for (int r = 0; r < RB; r++) acc[r] = 0.f;
    #pragma unroll 4
    for (int k = 0; k < FIN; k++) {
        float w = W[k * HH + col];
        const float4* sv = reinterpret_cast<const float4*>(&S[k * RB]);
        #pragma unroll
        for (int rr = 0; rr < RB / 4; rr++) {
            float4 v = sv[rr];
            acc[rr * 4 + 0] += v.x * w;
            acc[rr * 4 + 1] += v.y * w;
            acc[rr * 4 + 2] += v.z * w;
            acc[rr * 4 + 3] += v.w * w;
        }
    }
    if (!isG) {
        float b = resb[col];
        #pragma unroll
        for (int r = 0; r < RB; r++) s_res[r * HH + col] = acc[r] + b;
    }
    __syncthreads();
    if (isG) {
        float b = g1b[col];
        #pragma unroll
        for (int r = 0; r < RB; r++)
            g_h1[(r0 + r) * HH + col] = fmaxf(acc[r] + b, 0.f) + s_res[r * HH + col];
    }
}

// GEMM2: Q = h1 @ g2W. 128 threads, 16 rows/block.
__global__ void __launch_bounds__(128) k_gemm2(const float* __restrict__ g2W) {
    __shared__ float s_h[HH * RB];           // [k][r]
    int r0 = blockIdx.x * RB;
    int t = threadIdx.x;
    for (int u = t; u < HH * RB; u += 128) {
        int r = u >> 7, k = u & 127;
        s_h[k * RB + r] = g_h1[(r0 + r) * HH + k];
    }
    __syncthreads();
    float acc[RB];
    #pragma unroll
    for (int r = 0; r < RB; r++) acc[r] = 0.f;
    #pragma unroll 4
    for (int k = 0; k < HH; k++) {
        float w = g2W[k * HH + t];
        const float4* hv = reinterpret_cast<const float4*>(&s_h[k * RB]);
        #pragma unroll
        for (int rr = 0; rr < RB / 4; rr++) {
            float4 v = hv[rr];
            acc[rr * 4 + 0] += v.x * w;
            acc[rr * 4 + 1] += v.y * w;
            acc[rr * 4 + 2] += v.z * w;
            acc[rr * 4 + 3] += v.w * w;
        }
    }
    #pragma unroll
    for (int r = 0; r < RB; r++) g_Q[(r0 + r) * HH + t] = acc[r];
}

// SpMM2: h2 = relu(A_n Q + g2b), rowsum. Warp per row, float4 per lane.
// Last block: pooling softmax stats.
__global__ void __launch_bounds__(128) k_spmm2(const float* __restrict__ g2b) {
    __shared__ int   s_cols[4][CAP];
    __shared__ float s_dinv[4][CAP];
    __shared__ float s_m[4];
    __shared__ float s_bm;
    __shared__ int   s_last;
    int t = threadIdx.x, wid = t >> 5, lane = t & 31;
    int r = blockIdx.x * 4 + wid;
    int cnt = min(g_cnt[r], CAP);
    for (int k = lane; k < cnt; k += 32) {
        int c = g_cols[r * CAP + k];
        s_cols[wid][k] = c;
        s_dinv[wid][k] = rsqrtf((float)(min(g_cnt[c], CAP) + 1));
    }
    __syncwarp();
    float dr = rsqrtf((float)(cnt + 1));
    const float4* Qv = reinterpret_cast<const float4*>(g_Q);
    float4 self = Qv[r * 32 + lane];
    float a0 = dr * self.x, a1 = dr * self.y, a2 = dr * self.z, a3 = dr * self.w;
    float b0 = 0.f, b1 = 0.f, b2 = 0.f, b3 = 0.f;
    int k = 0;
    #pragma unroll 2
    for (; k + 1 < cnt; k += 2) {
        int   c0 = s_cols[wid][k],   c1 = s_cols[wid][k + 1];
        float d0 = s_dinv[wid][k],   d1 = s_dinv[wid][k + 1];
        float4 v0 = Qv[c0 * 32 + lane];
        float4 v1 = Qv[c1 * 32 + lane];
        a0 += d0 * v0.x; a1 += d0 * v0.y; a2 += d0 * v0.z; a3 += d0 * v0.w;
        b0 += d1 * v1.x; b1 += d1 * v1.y; b2 += d1 * v1.z; b3 += d1 * v1.w;
    }
    if (k < cnt) {
        int c = s_cols[wid][k]; float d = s_dinv[wid][k];
        float4 v = Qv[c * 32 + lane];
        a0 += d * v.x; a1 += d * v.y; a2 += d * v.z; a3 += d * v.w;
    }
    float4 bias = reinterpret_cast<const float4*>(g2b)[lane];
    float h0 = fmaxf(dr * (a0 + b0) + bias.x, 0.f);
    float h1v = fmaxf(dr * (a1 + b1) + bias.y, 0.f);
    float h2v = fmaxf(dr * (a2 + b2) + bias.z, 0.f);
    float h3 = fmaxf(dr * (a3 + b3) + bias.w, 0.f);
    reinterpret_cast<float4*>(g_h2)[r * 32 + lane] = make_float4(h0, h1v, h2v, h3);
    float v = h0 + h1v + h2v + h3;
    #pragma unroll
    for (int o = 16; o > 0; o >>= 1) v += __shfl_down_sync(0xffffffffu, v, o);
    if (lane == 0) g_rowsum[r] = v;

    __syncthreads();
    __threadfence();
    if (t == 0) {
        int done = atomicAdd(&g_ctr0, 1);
        s_last = (done == (int)gridDim.x - 1);
    }
    __syncthreads();
    if (!s_last) return;
    float m = -1e30f;
    for (int j = t; j < NN; j += 128) m = fmaxf(m, g_rowsum[j]);
    #pragma unroll
    for (int o = 16; o > 0; o >>= 1) m = fmaxf(m, __shfl_down_sync(0xffffffffu, m, o));
    if ((t & 31) == 0) s_m[t >> 5] = m;
    __syncthreads();
    if (t == 0) s_bm = fmaxf(fmaxf(s_m[0], s_m[1]), fmaxf(s_m[2], s_m[3]));
    __syncthreads();
    float bm = s_bm;
    float s = 0.f;
    for (int j = t; j < NN; j += 128) s += expf(g_rowsum[j] - bm);
    #pragma unroll
    for (int o = 16; o > 0; o >>= 1) s += __shfl_down_sync(0xffffffffu, s, o);
    __syncthreads();
    if ((t & 31) == 0) s_m[t >> 5] = s;
    __syncthreads();
    if (t == 0) {
        g_red[0] = bm;
        g_red[1] = s_m[0] + s_m[1] + s_m[2] + s_m[3];
        g_ctr0 = 0;
    }
}

// Pool + (last block) heads.
__global__ void __launch_bounds__(128) k_pool(const float* __restrict__ a1W, const float* __restrict__ a1b,
                        const float* __restrict__ lng, const float* __restrict__ lnb,
                        const float* __restrict__ c1W, const float* __restrict__ c1b,
                        const float* __restrict__ c2W, const float* __restrict__ c2b,
                        float* __restrict__ out, int out_size) {
    __shared__ float s_w[64];
    __shared__ float s_g[HH], s_z[HH], s_c[64];
    __shared__ float sm[4];
    __shared__ int   s_last;
    int t = threadIdx.x;
    int r0 = blockIdx.x * 64;
    if (t < 64) s_w[t] = expf(g_rowsum[r0 + t] - g_red[0]) * (1.0f / g_red[1]);
    __syncthreads();
    float acc = 0.f;
    #pragma unroll 4
    for (int j = 0; j < 64; j++) acc += s_w[j] * g_h2[(r0 + j) * HH + t];
    atomicAdd(&g_graph[t], acc);

    __threadfence();
    if (t == 0) {
        int done = atomicAdd(&g_ctr1, 1);
        s_last = (done == (int)gridDim.x - 1);
    }
    __syncthreads();
    if (!s_last) return;

    s_g[t] = g_graph[t];
    __syncthreads();
    if (t < 64) {
        float a = a1b[t];
        #pragma unroll 8
        for (int k = 0; k < HH; k++) a += s_g[k] * a1W[k * 64 + t];
        g_af[t] = fmaxf(a, 0.f);
    }
    float v = s_g[t];
    #pragma unroll
    for (int o = 16; o > 0; o >>= 1) v += __shfl_down_sync(0xffffffffu, v, o);
    if ((t & 31) == 0) sm[t >> 5] = v;
    __syncthreads();
    float mu = (sm[0] + sm[1] + sm[2] + sm[3]) * (1.0f / HH);
    __syncthreads();
    float d = s_g[t] - mu;
    float v2 = d * d;
    #pragma unroll
    for (int o = 16; o > 0; o >>= 1) v2 += __shfl_down_sync(0xffffffffu, v2, o);
    if ((t & 31) == 0) sm[t >> 5] = v2;
    __syncthreads();
    float var = (sm[0] + sm[1] + sm[2] + sm[3]) * (1.0f / HH);
    s_z[t] = d / sqrtf(var + 1e-5f) * lng[t] + lnb[t];
    __syncthreads();
    if (t < 64) {
        float c = c1b[t];
        #pragma unroll 8
        for (int k = 0; k < HH; k++) c += s_z[k] * c1W[k * 64 + t];
        s_c[t] = fmaxf(c, 0.f);
    }
    __syncthreads();
    if (t == 0) {
        float val = c2b[0];
        #pragma unroll 8
        for (int j = 0; j < 64; j++) val += s_c[j] * c2W[j];
        if (out_size > NN) out[NN] = val;
        g_ctr1 = 0;
    }
}

// Actor logits; last block computes softmax and writes action probs.
__global__ void __launch_bounds__(256) k_act(const float* __restrict__ a2W, const float* __restrict__ a2b,
                       float* __restrict__ out) {
    __shared__ float s_af[64];
    __shared__ float sm[8];
    __shared__ float s_bm;
    __shared__ int   s_last;
    int t = threadIdx.x;
    if (t < 64) s_af[t] = g_af[t];
    __syncthreads();
    int o = blockIdx.x * 256 + t;
    float acc = a2b[o];
    #pragma unroll
    for (int j = 0; j < 64; j++) acc += s_af[j] * a2W[j * AA + o];
    g_logits[o] = acc;

    __threadfence();
    if (t == 0) {
        int done = atomicAdd(&g_ctr2, 1);
        s_last = (done == (int)gridDim.x - 1);
    }
    __syncthreads();
    if (!s_last) return;

    float m = -1e30f;
    for (int j = t; j < AA; j += 256) m = fmaxf(m, g_logits[j]);
    #pragma unroll
    for (int ofs = 16; ofs > 0; ofs >>= 1) m = fmaxf(m, __shfl_down_sync(0xffffffffu, m, ofs));
    if ((t & 31) == 0) sm[t >> 5] = m;
    __syncthreads();
    if (t == 0) {
        float x = sm[0];
        #pragma unroll
        for (int j = 1; j < 8; j++) x = fmaxf(x, sm[j]);
        s_bm = x;
    }
    __syncthreads();
    float bm = s_bm;
    float s = 0.f;
    for (int j = t; j < AA; j += 256) s += expf(g_logits[j] - bm);
    #pragma unroll
    for (int ofs = 16; ofs > 0; ofs >>= 1) s += __shfl_down_sync(0xffffffffu, s, ofs);
    __syncthreads();
    if ((t & 31) == 0) sm[t >> 5] = s;
    __syncthreads();
    if (t == 0) {
        float x = 0.f;
        #pragma unroll
        for (int j = 0; j < 8; j++) x += sm[j];
        s_bm = 1.0f / x;
        g_ctr2 = 0;
    }
    __syncthreads();
    float inv = s_bm;
    for (int j = t; j < AA; j += 256) out[j] = expf(g_logits[j] - bm) * inv;
}

// ---------------- launch ----------------
extern "C" void kernel_launch(void* const* d_in, const int* in_sizes, int n_in,
                              void* d_out, int out_size) {
    const float* x    = (const float*)d_in[0];
    const int*   ei   = (const int*)  d_in[1];
    int E = in_sizes[1] / 2;
    const float* g1W  = (const float*)d_in[2];
    const float* g1b  = (const float*)d_in[3];
    const float* g2W  = (const float*)d_in[4];
    const float* g2b  = (const float*)d_in[5];
    const float* resW = (const float*)d_in[6];
    const float* resb = (const float*)d_in[7];
    const float* a1W  = (const float*)d_in[8];
    const float* a1b  = (const float*)d_in[9];
    const float* a2W  = (const float*)d_in[10];
    const float* a2b  = (const float*)d_in[11];
    const float* lng  = (const float*)d_in[12];
    const float* lnb  = (const float*)d_in[13];
    const float* c1W  = (const float*)d_in[14];
    const float* c1b  = (const float*)d_in[15];
    const float* c2W  = (const float*)d_in[16];
    const float* c2b  = (const float*)d_in[17];
    float* out = (float*)d_out;

    k_init <<<1024, 512>>>(ei);
    k_dedup<<<(E + 255) / 256, 256>>>(ei, E);
    k_spmmx<<<NN / 4, 128>>>(x);
    k_l1   <<<NN / RB, 256>>>(x, g1W, g1b, resW, resb);
    k_gemm2<<<NN / RB, 128>>>(g2W);
    k_spmm2<<<NN / 4, 128>>>(g2b);
    k_pool <<<128, 128>>>(a1W, a1b, lng, lnb, c1W, c1b, c2W, c2b, out, out_size);
    k_act  <<<32, 256>>>(a2W, a2b, out);
}